// round 12
// baseline (speedup 1.0000x reference)
#include <cuda_runtime.h>
#include <cuda_fp16.h>
#include <math.h>
#include <stdint.h>

#define NN 50000
#define EE 800000
#define ET (EE + NN)
#define FIN 128
#define H1DIM 256
#define H2DIM 128
#define NGRAPH 64
#define NEG_SLOPE 0.2f
#define NBLK 49   // ceil(NN/1024)
#define WCAP 64   // per-warp SMEM edge-weight cache capacity

// ---------------- scratch ----------------------------------------------------
__device__ __align__(16) float  g_h1[(size_t)NN * H1DIM];
__device__ __align__(16) __half g_h1h[(size_t)NN * H1DIM];
__device__ __align__(16) float  g_out1[(size_t)NN * H1DIM];
__device__ __align__(16) float  g_h2[(size_t)NN * H2DIM];
__device__ __align__(16) __half g_h2h[(size_t)NN * H2DIM];
__device__ __align__(16) float  g_out2[(size_t)NN * H2DIM];
__device__ __align__(16) float  g_es1[NN * 4];
__device__ __align__(16) float  g_ed1[NN * 4];
__device__ float g_es2[NN];
__device__ float g_ed2[NN];
__device__ int   g_cnt[NN];      // zero at start of every run (scan3 resets)
__device__ int   g_off[NN + 1];
__device__ int   g_rank[ET];
__device__ int   g_esrc[ET];
__device__ int   g_bsum[NBLK];
__device__ int   g_boff[NBLK];

// ---------------- CSR build --------------------------------------------------
__global__ void count_kernel(const int* __restrict__ ei) {
    int e = blockIdx.x * blockDim.x + threadIdx.x;
    if (e >= ET) return;
    int dst = (e < EE) ? ei[EE + e] : (e - EE);
    g_rank[e] = atomicAdd(&g_cnt[dst], 1);
}

__global__ void scan1_kernel() {
    __shared__ int sdata[1024];
    int b = blockIdx.x, tid = threadIdx.x;
    int i = b * 1024 + tid;
    int v = (i < NN) ? g_cnt[i] : 0;
    sdata[tid] = v;
    __syncthreads();
    #pragma unroll
    for (int d = 1; d < 1024; d <<= 1) {
        int t = (tid >= d) ? sdata[tid - d] : 0;
        __syncthreads();
        sdata[tid] += t;
        __syncthreads();
    }
    if (i < NN) g_off[i] = sdata[tid] - v;
    if (tid == 1023) g_bsum[b] = sdata[1023];
}

__global__ void scan2_kernel() {
    int t = threadIdx.x;            // 64 threads
    int lane = t & 31, w = t >> 5;
    int v = (t < NBLK) ? g_bsum[t] : 0;
    int x = v;
    #pragma unroll
    for (int d = 1; d < 32; d <<= 1) {
        int y = __shfl_up_sync(0xffffffffu, x, d);
        if (lane >= d) x += y;
    }
    __shared__ int wt[2];
    if (lane == 31) wt[w] = x;
    __syncthreads();
    if (w == 1) x += wt[0];
    if (t < NBLK) g_boff[t] = x - v;
}

__global__ void scan3_kernel() {
    int i = blockIdx.x * blockDim.x + threadIdx.x;
    if (i >= NN) return;
    g_off[i] = g_off[i] + g_boff[i >> 10];
    g_cnt[i] = 0;                    // reset for next graph replay
    if (i == 0) g_off[NN] = ET;
}

__global__ void fill_kernel(const int* __restrict__ ei) {
    int e = blockIdx.x * blockDim.x + threadIdx.x;
    if (e >= ET) return;
    int src, dst;
    if (e < EE) { src = ei[e]; dst = ei[EE + e]; }
    else        { src = e - EE; dst = e - EE; }
    g_esrc[g_off[dst] + g_rank[e]] = src;
}

// ---------------- single-pass TF32 tensor-core GEMM --------------------------
#define BM 128
#define BN 128
#define BK 16
#define PADK 8

__device__ __forceinline__ float4 ldg4(const float* p) { return *(const float4*)p; }

__device__ __forceinline__ uint32_t f2tf(float x) {
    uint32_t u;
    asm("cvt.rna.tf32.f32 %0, %1;" : "=r"(u) : "f"(x));
    return u;
}

__device__ __forceinline__ void mma8(float* c, const uint32_t* a, const uint32_t* b) {
    asm volatile(
        "mma.sync.aligned.m16n8k8.row.col.f32.tf32.tf32.f32 "
        "{%0,%1,%2,%3},{%4,%5,%6,%7},{%8,%9},{%0,%1,%2,%3};"
        : "+f"(c[0]), "+f"(c[1]), "+f"(c[2]), "+f"(c[3])
        : "r"(a[0]), "r"(a[1]), "r"(a[2]), "r"(a[3]), "r"(b[0]), "r"(b[1]));
}

__device__ __forceinline__ void gemm_body(
    const float* __restrict__ A, const float* __restrict__ B,
    float* __restrict__ C, __half* __restrict__ Ch, int M, int N, int K)
{
    __shared__ uint32_t Ahi[2][BK][BM + PADK];
    __shared__ uint32_t Bhi[2][BK][BN + PADK];

    const int tid  = threadIdx.x;
    const int lane = tid & 31;
    const int wid  = tid >> 5;
    const int warp_m = wid >> 2;
    const int warp_n = wid & 3;
    const int bm = blockIdx.y * BM, bn = blockIdx.x * BN;
    const int tg = lane & 3;
    const int tr = lane >> 2;

    const int ar = tid & 127, ac = (tid >> 7) * 8;
    const int br = tid >> 4, bc = (tid & 15) * 8;

    float c[4][4][4];
    #pragma unroll
    for (int mt = 0; mt < 4; mt++)
        #pragma unroll
        for (int nt = 0; nt < 4; nt++)
            #pragma unroll
            for (int r = 0; r < 4; r++) c[mt][nt][r] = 0.f;

    float4 pa0, pa1, pb0, pb1;
    auto LDG = [&](int k0) {
        if (bm + ar < M) {
            pa0 = ldg4(A + (size_t)(bm + ar) * K + k0 + ac);
            pa1 = ldg4(A + (size_t)(bm + ar) * K + k0 + ac + 4);
        } else {
            pa0 = make_float4(0.f,0.f,0.f,0.f);
            pa1 = pa0;
        }
        pb0 = ldg4(B + (size_t)(k0 + br) * N + bn + bc);
        pb1 = ldg4(B + (size_t)(k0 + br) * N + bn + bc + 4);
    };
    auto STS = [&](int buf) {
        float av[8] = {pa0.x, pa0.y, pa0.z, pa0.w, pa1.x, pa1.y, pa1.z, pa1.w};
        #pragma unroll
        for (int i = 0; i < 8; i++)
            Ahi[buf][ac + i][ar] = f2tf(av[i]);
        *(uint4*)&Bhi[buf][br][bc] =
            make_uint4(f2tf(pb0.x), f2tf(pb0.y), f2tf(pb0.z), f2tf(pb0.w));
        *(uint4*)&Bhi[buf][br][bc + 4] =
            make_uint4(f2tf(pb1.x), f2tf(pb1.y), f2tf(pb1.z), f2tf(pb1.w));
    };

    LDG(0);
    STS(0);
    __syncthreads();

    const int T = K / BK;
    for (int t = 0; t < T; t++) {
        int cur = t & 1;
        if (t + 1 < T) LDG((t + 1) * BK);

        #pragma unroll
        for (int ks = 0; ks < 2; ks++) {
            const int kk = ks * 8;
            uint32_t a[4][4], b[4][2];
            #pragma unroll
            for (int mt = 0; mt < 4; mt++) {
                int mb = warp_m * 64 + mt * 16;
                a[mt][0] = Ahi[cur][kk + tg    ][mb + tr];
                a[mt][1] = Ahi[cur][kk + tg    ][mb + tr + 8];
                a[mt][2] = Ahi[cur][kk + tg + 4][mb + tr];
                a[mt][3] = Ahi[cur][kk + tg + 4][mb + tr + 8];
            }
            #pragma unroll
            for (int nt = 0; nt < 4; nt++) {
                int nb = warp_n * 32 + nt * 8;
                b[nt][0] = Bhi[cur][kk + tg    ][nb + tr];
                b[nt][1] = Bhi[cur][kk + tg + 4][nb + tr];
            }
            #pragma unroll
            for (int mt = 0; mt < 4; mt++)
                #pragma unroll
                for (int nt = 0; nt < 4; nt++)
                    mma8(c[mt][nt], a[mt], b[nt]);
        }

        if (t + 1 < T) { STS(cur ^ 1); __syncthreads(); }
    }

    #pragma unroll
    for (int mt = 0; mt < 4; mt++) {
        int row0 = bm + warp_m * 64 + mt * 16 + tr;
        int row1 = row0 + 8;
        #pragma unroll
        for (int nt = 0; nt < 4; nt++) {
            int col = bn + warp_n * 32 + nt * 8 + tg * 2;
            if (row0 < M) {
                *(float2*)(C + (size_t)row0 * N + col) = make_float2(c[mt][nt][0], c[mt][nt][1]);
                *(__half2*)(Ch + (size_t)row0 * N + col) =
                    __float22half2_rn(make_float2(c[mt][nt][0], c[mt][nt][1]));
            }
            if (row1 < M) {
                *(float2*)(C + (size_t)row1 * N + col) = make_float2(c[mt][nt][2], c[mt][nt][3]);
                *(__half2*)(Ch + (size_t)row1 * N + col) =
                    __float22half2_rn(make_float2(c[mt][nt][2], c[mt][nt][3]));
            }
        }
    }
}

__global__ __launch_bounds__(256) void gemm1_kernel(
    const float* __restrict__ x, const float* __restrict__ W1)
{
    gemm_body(x, W1, g_h1, g_h1h, NN, H1DIM, FIN);
}

__global__ __launch_bounds__(256) void gemm2_kernel(
    const float* __restrict__ W2)
{
    gemm_body(g_out1, W2, g_h2, g_h2h, NN, H2DIM, H1DIM);
}

// ---------------- attention coefficients ------------------------------------
__global__ void coef1_kernel(const float* __restrict__ a_s, const float* __restrict__ a_d) {
    int idx = blockIdx.x * blockDim.x + threadIdx.x;
    if (idx >= NN * 4) return;
    int node = idx >> 2, head = idx & 3;
    const float4* row = (const float4*)(g_h1 + (size_t)node * H1DIM + head * 64);
    const float4* as = (const float4*)(a_s + head * 64);
    const float4* ad = (const float4*)(a_d + head * 64);
    float s = 0.f, d = 0.f;
    #pragma unroll
    for (int c = 0; c < 16; c++) {
        float4 h = row[c];
        float4 sa = as[c], da = ad[c];
        s = fmaf(h.x, sa.x, fmaf(h.y, sa.y, fmaf(h.z, sa.z, fmaf(h.w, sa.w, s))));
        d = fmaf(h.x, da.x, fmaf(h.y, da.y, fmaf(h.z, da.z, fmaf(h.w, da.w, d))));
    }
    g_es1[idx] = s;
    g_ed1[idx] = d;
}

__global__ void coef2_kernel(const float* __restrict__ a_s, const float* __restrict__ a_d) {
    int node = blockIdx.x * blockDim.x + threadIdx.x;
    if (node >= NN) return;
    const float4* row = (const float4*)(g_h2 + (size_t)node * H2DIM);
    const float4* as = (const float4*)a_s;
    const float4* ad = (const float4*)a_d;
    float s = 0.f, d = 0.f;
    #pragma unroll
    for (int c = 0; c < 32; c++) {
        float4 h = row[c];
        float4 sa = as[c], da = ad[c];
        s = fmaf(h.x, sa.x, fmaf(h.y, sa.y, fmaf(h.z, sa.z, fmaf(h.w, sa.w, s))));
        d = fmaf(h.x, da.x, fmaf(h.y, da.y, fmaf(h.z, da.z, fmaf(h.w, da.w, d))));
    }
    g_es2[node] = s;
    g_ed2[node] = d;
}

__device__ __forceinline__ float elu1(float x)  { return x > 0.f ? x : expm1f(x); }
__device__ __forceinline__ float lrelu(float x) { return x > 0.f ? x : NEG_SLOPE * x; }

// ---------------- fused softmax + aggregation (warp per dst) -----------------
// Pass A computes exp weights once and caches them in per-warp SMEM (cap WCAP);
// pass B reads them via broadcast LDS. Warp-uniform fallback recomputes if
// degree > WCAP (vanishingly rare: degree ~ Poisson(17)).
__global__ __launch_bounds__(256) void agg1_kernel(const float* __restrict__ b1) {
    __shared__ float4 swc[8][WCAP];
    int dst  = (blockIdx.x * blockDim.x + threadIdx.x) >> 5;
    int lane = threadIdx.x & 31;
    int wslot = (threadIdx.x >> 5);
    if (dst >= NN) return;
    int start = g_off[dst], end = g_off[dst + 1];
    float4 ed = *(const float4*)&g_ed1[dst * 4];

    // pass A: lane-parallel exp sums + SMEM weight cache
    float s0=0.f,s1=0.f,s2=0.f,s3=0.f;
    for (int j = start + lane; j < end; j += 32) {
        int src = g_esrc[j];
        float4 es = *(const float4*)&g_es1[src * 4];
        float w0 = __expf(lrelu(es.x + ed.x));
        float w1 = __expf(lrelu(es.y + ed.y));
        float w2 = __expf(lrelu(es.z + ed.z));
        float w3 = __expf(lrelu(es.w + ed.w));
        s0 += w0; s1 += w1; s2 += w2; s3 += w3;
        int o = j - start;
        if (o < WCAP) swc[wslot][o] = make_float4(w0, w1, w2, w3);
    }
    __syncwarp();
    #pragma unroll
    for (int off = 16; off; off >>= 1) {
        s0 += __shfl_xor_sync(0xffffffffu, s0, off);
        s1 += __shfl_xor_sync(0xffffffffu, s1, off);
        s2 += __shfl_xor_sync(0xffffffffu, s2, off);
        s3 += __shfl_xor_sync(0xffffffffu, s3, off);
    }
    float i0 = 1.f/s0, i1 = 1.f/s1, i2 = 1.f/s2, i3 = 1.f/s3;

    // pass B: serial edges, weights from SMEM, feature-parallel half gathers
    int hsel = lane >> 4;
    float ia = hsel ? i1 : i0, ib = hsel ? i3 : i2;
    float eda = hsel ? ed.y : ed.x, edb = hsel ? ed.w : ed.z;

    float4 acc0 = make_float4(0.f,0.f,0.f,0.f);
    float4 acc1 = make_float4(0.f,0.f,0.f,0.f);

    #pragma unroll 4
    for (int j = start; j < end; j++) {
        int o = j - start;
        int src = g_esrc[j];
        float wa, wb;
        if (o < WCAP) {
            float4 w4 = swc[wslot][o];
            wa = (hsel ? w4.y : w4.x) * ia;
            wb = (hsel ? w4.w : w4.z) * ib;
        } else {
            float4 es = *(const float4*)&g_es1[src * 4];
            wa = __expf(lrelu((hsel ? es.y : es.x) + eda)) * ia;
            wb = __expf(lrelu((hsel ? es.w : es.z) + edb)) * ib;
        }
        const float2* row = (const float2*)(g_h1h + (size_t)src * H1DIM);
        float2 q0 = row[lane];
        float2 q1 = row[lane + 32];
        float2 f0 = __half22float2(*(__half2*)&q0.x);
        float2 f1 = __half22float2(*(__half2*)&q0.y);
        float2 f2 = __half22float2(*(__half2*)&q1.x);
        float2 f3 = __half22float2(*(__half2*)&q1.y);
        acc0.x = fmaf(wa, f0.x, acc0.x); acc0.y = fmaf(wa, f0.y, acc0.y);
        acc0.z = fmaf(wa, f1.x, acc0.z); acc0.w = fmaf(wa, f1.y, acc0.w);
        acc1.x = fmaf(wb, f2.x, acc1.x); acc1.y = fmaf(wb, f2.y, acc1.y);
        acc1.z = fmaf(wb, f3.x, acc1.z); acc1.w = fmaf(wb, f3.y, acc1.w);
    }

    int c0 = lane * 4, c1 = 128 + lane * 4;
    float4 bb0 = *(const float4*)&b1[c0];
    float4 bb1 = *(const float4*)&b1[c1];
    float4 o0 = make_float4(elu1(acc0.x + bb0.x), elu1(acc0.y + bb0.y),
                            elu1(acc0.z + bb0.z), elu1(acc0.w + bb0.w));
    float4 o1 = make_float4(elu1(acc1.x + bb1.x), elu1(acc1.y + bb1.y),
                            elu1(acc1.z + bb1.z), elu1(acc1.w + bb1.w));
    *(float4*)(g_out1 + (size_t)dst * H1DIM + c0) = o0;
    *(float4*)(g_out1 + (size_t)dst * H1DIM + c1) = o1;
}

__global__ __launch_bounds__(256) void agg2_kernel(const float* __restrict__ b2) {
    __shared__ float swc[8][WCAP];
    int dst  = (blockIdx.x * blockDim.x + threadIdx.x) >> 5;
    int lane = threadIdx.x & 31;
    int wslot = (threadIdx.x >> 5);
    if (dst >= NN) return;
    int start = g_off[dst], end = g_off[dst + 1];
    float edv = g_ed2[dst];

    float s = 0.f;
    for (int j = start + lane; j < end; j += 32) {
        int src = g_esrc[j];
        float w = __expf(lrelu(g_es2[src] + edv));
        s += w;
        int o = j - start;
        if (o < WCAP) swc[wslot][o] = w;
    }
    __syncwarp();
    #pragma unroll
    for (int off = 16; off; off >>= 1)
        s += __shfl_xor_sync(0xffffffffu, s, off);
    float inv = 1.f / s;

    float4 acc = make_float4(0.f,0.f,0.f,0.f);
    #pragma unroll 4
    for (int j = start; j < end; j++) {
        int o = j - start;
        int src = g_esrc[j];
        float wt = ((o < WCAP) ? swc[wslot][o]
                               : __expf(lrelu(g_es2[src] + edv))) * inv;
        const float2* row = (const float2*)(g_h2h + (size_t)src * H2DIM);
        float2 q = row[lane];
        float2 f0 = __half22float2(*(__half2*)&q.x);
        float2 f1 = __half22float2(*(__half2*)&q.y);
        acc.x = fmaf(wt, f0.x, acc.x); acc.y = fmaf(wt, f0.y, acc.y);
        acc.z = fmaf(wt, f1.x, acc.z); acc.w = fmaf(wt, f1.y, acc.w);
    }

    int c0 = lane * 4;
    float4 bb = *(const float4*)&b2[c0];
    float4 o = make_float4(elu1(acc.x + bb.x), elu1(acc.y + bb.y),
                           elu1(acc.z + bb.z), elu1(acc.w + bb.w));
    *(float4*)(g_out2 + (size_t)dst * H2DIM + c0) = o;
}

// ---------------- pooling + FC + log_softmax ---------------------------------
__device__ __forceinline__ int lb_i(const int* a, int n, int v) {
    int lo = 0, hi = n;
    while (lo < hi) { int mid = (lo + hi) >> 1; if (a[mid] < v) lo = mid + 1; else hi = mid; }
    return lo;
}

__global__ void pool_fc_kernel(const int* __restrict__ batch,
                               const float* __restrict__ fc_w,
                               const float* __restrict__ fc_b,
                               float* __restrict__ out)
{
    int g = blockIdx.x;
    int tid = threadIdx.x;
    __shared__ float sp[128];
    __shared__ float slog[10];
    int lo = lb_i(batch, NN, g);
    int hi = lb_i(batch, NN, g + 1);
    float s = 0.f;
    for (int i = lo; i < hi; i++) s += g_out2[(size_t)i * H2DIM + tid];
    float cnt = (float)(hi - lo);
    sp[tid] = s / fmaxf(cnt, 1.f);
    __syncthreads();
    if (tid < 10) {
        float l = fc_b[tid];
        #pragma unroll 16
        for (int c = 0; c < 128; c++) l = fmaf(sp[c], fc_w[c * 10 + tid], l);
        slog[tid] = l;
    }
    __syncthreads();
    if (tid == 0) {
        float mx = -1e30f;
        #pragma unroll
        for (int k = 0; k < 10; k++) mx = fmaxf(mx, slog[k]);
        float sum = 0.f;
        #pragma unroll
        for (int k = 0; k < 10; k++) sum += expf(slog[k] - mx);
        float lse = mx + logf(sum);
        #pragma unroll
        for (int k = 0; k < 10; k++) out[g * 10 + k] = slog[k] - lse;
    }
}

// ---------------- launch -----------------------------------------------------
extern "C" void kernel_launch(void* const* d_in, const int* in_sizes, int n_in,
                              void* d_out, int out_size)
{
    const float* x     = (const float*)d_in[0];
    const int*   ei    = (const int*)d_in[1];
    const int*   batch = (const int*)d_in[2];
    const float* W1    = (const float*)d_in[3];
    const float* a_s1  = (const float*)d_in[4];
    const float* a_d1  = (const float*)d_in[5];
    const float* b1    = (const float*)d_in[6];
    const float* W2    = (const float*)d_in[7];
    const float* a_s2  = (const float*)d_in[8];
    const float* a_d2  = (const float*)d_in[9];
    const float* b2    = (const float*)d_in[10];
    const float* fc_w  = (const float*)d_in[11];
    const float* fc_b  = (const float*)d_in[12];
    float* out = (float*)d_out;

    count_kernel<<<(ET + 255) / 256, 256>>>(ei);
    scan1_kernel<<<NBLK, 1024>>>();
    scan2_kernel<<<1, 64>>>();
    scan3_kernel<<<(NN + 255) / 256, 256>>>();
    fill_kernel<<<(ET + 255) / 256, 256>>>(ei);

    {
        dim3 grid(H1DIM / BN, (NN + BM - 1) / BM);
        gemm1_kernel<<<grid, 256>>>(x, W1);
    }
    coef1_kernel<<<(NN * 4 + 255) / 256, 256>>>(a_s1, a_d1);
    agg1_kernel<<<(NN * 32 + 255) / 256, 256>>>(b1);

    {
        dim3 grid(H2DIM / BN, (NN + BM - 1) / BM);
        gemm2_kernel<<<grid, 256>>>(W2);
    }
    coef2_kernel<<<(NN + 255) / 256, 256>>>(a_s2, a_d2);
    agg2_kernel<<<(NN * 32 + 255) / 256, 256>>>(b2);

    pool_fc_kernel<<<NGRAPH, 128>>>(batch, fc_w, fc_b, out);
}

// round 13
// speedup vs baseline: 1.4893x; 1.4893x over previous
#include <cuda_runtime.h>
#include <cuda_fp16.h>
#include <math.h>
#include <stdint.h>

#define NN 50000
#define EE 800000
#define ET (EE + NN)
#define FIN 128
#define H1DIM 256
#define H2DIM 128
#define NGRAPH 64
#define NEG_SLOPE 0.2f
#define NBLK 49   // ceil(NN/1024)

// ---------------- scratch ----------------------------------------------------
__device__ __align__(16) float  g_h1[(size_t)NN * H1DIM];
__device__ __align__(16) __half g_h1h[(size_t)NN * H1DIM];
__device__ __align__(16) float  g_out1[(size_t)NN * H1DIM];
__device__ __align__(16) float  g_h2[(size_t)NN * H2DIM];
__device__ __align__(16) __half g_h2h[(size_t)NN * H2DIM];
__device__ __align__(16) float  g_out2[(size_t)NN * H2DIM];
__device__ __align__(16) float  g_es1[NN * 4];
__device__ __align__(16) float  g_ed1[NN * 4];
__device__ __align__(16) float  g_ew1[(size_t)ET * 4];  // unnormalized exp weights L1
__device__ __align__(16) float  g_ew2[ET];              // unnormalized exp weights L2
__device__ float g_es2[NN];
__device__ float g_ed2[NN];
__device__ int   g_cnt[NN];
__device__ int   g_off[NN + 1];
__device__ int   g_rank[ET];
__device__ int   g_esrc[ET];
__device__ int   g_edst[ET];
__device__ int   g_bsum[NBLK];
__device__ int   g_boff[NBLK];

// ---------------- CSR build --------------------------------------------------
__global__ void zero_counts_kernel() {
    int i = blockIdx.x * blockDim.x + threadIdx.x;
    if (i < NN) g_cnt[i] = 0;
}

__global__ void count_kernel(const int* __restrict__ ei) {
    int e = blockIdx.x * blockDim.x + threadIdx.x;
    if (e >= ET) return;
    int dst = (e < EE) ? ei[EE + e] : (e - EE);
    g_rank[e] = atomicAdd(&g_cnt[dst], 1);
}

__global__ void scan1_kernel() {
    __shared__ int sdata[1024];
    int b = blockIdx.x, tid = threadIdx.x;
    int i = b * 1024 + tid;
    int v = (i < NN) ? g_cnt[i] : 0;
    sdata[tid] = v;
    __syncthreads();
    #pragma unroll
    for (int d = 1; d < 1024; d <<= 1) {
        int t = (tid >= d) ? sdata[tid - d] : 0;
        __syncthreads();
        sdata[tid] += t;
        __syncthreads();
    }
    if (i < NN) g_off[i] = sdata[tid] - v;
    if (tid == 1023) g_bsum[b] = sdata[1023];
}

__global__ void scan2_kernel() {
    int t = threadIdx.x;            // 64 threads
    int lane = t & 31, w = t >> 5;
    int v = (t < NBLK) ? g_bsum[t] : 0;
    int x = v;
    #pragma unroll
    for (int d = 1; d < 32; d <<= 1) {
        int y = __shfl_up_sync(0xffffffffu, x, d);
        if (lane >= d) x += y;
    }
    __shared__ int wt[2];
    if (lane == 31) wt[w] = x;
    __syncthreads();
    if (w == 1) x += wt[0];
    if (t < NBLK) g_boff[t] = x - v;
}

__global__ void scan3_kernel() {
    int i = blockIdx.x * blockDim.x + threadIdx.x;
    if (i >= NN) return;
    g_off[i] = g_off[i] + g_boff[i >> 10];
    if (i == 0) g_off[NN] = ET;
}

__global__ void fill_kernel(const int* __restrict__ ei) {
    int e = blockIdx.x * blockDim.x + threadIdx.x;
    if (e >= ET) return;
    int src, dst;
    if (e < EE) { src = ei[e]; dst = ei[EE + e]; }
    else        { src = e - EE; dst = e - EE; }
    int pos = g_off[dst] + g_rank[e];
    g_esrc[pos] = src;
    g_edst[pos] = dst;
}

// ---------------- single-pass TF32 tensor-core GEMM --------------------------
#define BM 128
#define BN 128
#define BK 16
#define PADK 8

__device__ __forceinline__ float4 ldg4(const float* p) { return *(const float4*)p; }

__device__ __forceinline__ uint32_t f2tf(float x) {
    uint32_t u;
    asm("cvt.rna.tf32.f32 %0, %1;" : "=r"(u) : "f"(x));
    return u;
}

__device__ __forceinline__ void mma8(float* c, const uint32_t* a, const uint32_t* b) {
    asm volatile(
        "mma.sync.aligned.m16n8k8.row.col.f32.tf32.tf32.f32 "
        "{%0,%1,%2,%3},{%4,%5,%6,%7},{%8,%9},{%0,%1,%2,%3};"
        : "+f"(c[0]), "+f"(c[1]), "+f"(c[2]), "+f"(c[3])
        : "r"(a[0]), "r"(a[1]), "r"(a[2]), "r"(a[3]), "r"(b[0]), "r"(b[1]));
}

__device__ __forceinline__ void gemm_body(
    const float* __restrict__ A, const float* __restrict__ B,
    float* __restrict__ C, __half* __restrict__ Ch, int M, int N, int K)
{
    __shared__ uint32_t Ahi[2][BK][BM + PADK];
    __shared__ uint32_t Bhi[2][BK][BN + PADK];

    const int tid  = threadIdx.x;
    const int lane = tid & 31;
    const int wid  = tid >> 5;
    const int warp_m = wid >> 2;
    const int warp_n = wid & 3;
    const int bm = blockIdx.y * BM, bn = blockIdx.x * BN;
    const int tg = lane & 3;
    const int tr = lane >> 2;

    const int ar = tid & 127, ac = (tid >> 7) * 8;
    const int br = tid >> 4, bc = (tid & 15) * 8;

    float c[4][4][4];
    #pragma unroll
    for (int mt = 0; mt < 4; mt++)
        #pragma unroll
        for (int nt = 0; nt < 4; nt++)
            #pragma unroll
            for (int r = 0; r < 4; r++) c[mt][nt][r] = 0.f;

    float4 pa0, pa1, pb0, pb1;
    auto LDG = [&](int k0) {
        if (bm + ar < M) {
            pa0 = ldg4(A + (size_t)(bm + ar) * K + k0 + ac);
            pa1 = ldg4(A + (size_t)(bm + ar) * K + k0 + ac + 4);
        } else {
            pa0 = make_float4(0.f,0.f,0.f,0.f);
            pa1 = pa0;
        }
        pb0 = ldg4(B + (size_t)(k0 + br) * N + bn + bc);
        pb1 = ldg4(B + (size_t)(k0 + br) * N + bn + bc + 4);
    };
    auto STS = [&](int buf) {
        float av[8] = {pa0.x, pa0.y, pa0.z, pa0.w, pa1.x, pa1.y, pa1.z, pa1.w};
        #pragma unroll
        for (int i = 0; i < 8; i++)
            Ahi[buf][ac + i][ar] = f2tf(av[i]);
        *(uint4*)&Bhi[buf][br][bc] =
            make_uint4(f2tf(pb0.x), f2tf(pb0.y), f2tf(pb0.z), f2tf(pb0.w));
        *(uint4*)&Bhi[buf][br][bc + 4] =
            make_uint4(f2tf(pb1.x), f2tf(pb1.y), f2tf(pb1.z), f2tf(pb1.w));
    };

    LDG(0);
    STS(0);
    __syncthreads();

    const int T = K / BK;
    for (int t = 0; t < T; t++) {
        int cur = t & 1;
        if (t + 1 < T) LDG((t + 1) * BK);

        #pragma unroll
        for (int ks = 0; ks < 2; ks++) {
            const int kk = ks * 8;
            uint32_t a[4][4], b[4][2];
            #pragma unroll
            for (int mt = 0; mt < 4; mt++) {
                int mb = warp_m * 64 + mt * 16;
                a[mt][0] = Ahi[cur][kk + tg    ][mb + tr];
                a[mt][1] = Ahi[cur][kk + tg    ][mb + tr + 8];
                a[mt][2] = Ahi[cur][kk + tg + 4][mb + tr];
                a[mt][3] = Ahi[cur][kk + tg + 4][mb + tr + 8];
            }
            #pragma unroll
            for (int nt = 0; nt < 4; nt++) {
                int nb = warp_n * 32 + nt * 8;
                b[nt][0] = Bhi[cur][kk + tg    ][nb + tr];
                b[nt][1] = Bhi[cur][kk + tg + 4][nb + tr];
            }
            #pragma unroll
            for (int mt = 0; mt < 4; mt++)
                #pragma unroll
                for (int nt = 0; nt < 4; nt++)
                    mma8(c[mt][nt], a[mt], b[nt]);
        }

        if (t + 1 < T) { STS(cur ^ 1); __syncthreads(); }
    }

    #pragma unroll
    for (int mt = 0; mt < 4; mt++) {
        int row0 = bm + warp_m * 64 + mt * 16 + tr;
        int row1 = row0 + 8;
        #pragma unroll
        for (int nt = 0; nt < 4; nt++) {
            int col = bn + warp_n * 32 + nt * 8 + tg * 2;
            if (row0 < M) {
                *(float2*)(C + (size_t)row0 * N + col) = make_float2(c[mt][nt][0], c[mt][nt][1]);
                *(__half2*)(Ch + (size_t)row0 * N + col) =
                    __float22half2_rn(make_float2(c[mt][nt][0], c[mt][nt][1]));
            }
            if (row1 < M) {
                *(float2*)(C + (size_t)row1 * N + col) = make_float2(c[mt][nt][2], c[mt][nt][3]);
                *(__half2*)(Ch + (size_t)row1 * N + col) =
                    __float22half2_rn(make_float2(c[mt][nt][2], c[mt][nt][3]));
            }
        }
    }
}

__global__ __launch_bounds__(256) void gemm1_kernel(
    const float* __restrict__ x, const float* __restrict__ W1)
{
    gemm_body(x, W1, g_h1, g_h1h, NN, H1DIM, FIN);
}

__global__ __launch_bounds__(256) void gemm2_kernel(
    const float* __restrict__ W2)
{
    gemm_body(g_out1, W2, g_h2, g_h2h, NN, H2DIM, H1DIM);
}

// ---------------- attention coefficients ------------------------------------
__global__ void coef1_kernel(const float* __restrict__ a_s, const float* __restrict__ a_d) {
    int idx = blockIdx.x * blockDim.x + threadIdx.x;
    if (idx >= NN * 4) return;
    int node = idx >> 2, head = idx & 3;
    const float4* row = (const float4*)(g_h1 + (size_t)node * H1DIM + head * 64);
    const float4* as = (const float4*)(a_s + head * 64);
    const float4* ad = (const float4*)(a_d + head * 64);
    float s = 0.f, d = 0.f;
    #pragma unroll
    for (int c = 0; c < 16; c++) {
        float4 h = row[c];
        float4 sa = as[c], da = ad[c];
        s = fmaf(h.x, sa.x, fmaf(h.y, sa.y, fmaf(h.z, sa.z, fmaf(h.w, sa.w, s))));
        d = fmaf(h.x, da.x, fmaf(h.y, da.y, fmaf(h.z, da.z, fmaf(h.w, da.w, d))));
    }
    g_es1[idx] = s;
    g_ed1[idx] = d;
}

__global__ void coef2_kernel(const float* __restrict__ a_s, const float* __restrict__ a_d) {
    int node = blockIdx.x * blockDim.x + threadIdx.x;
    if (node >= NN) return;
    const float4* row = (const float4*)(g_h2 + (size_t)node * H2DIM);
    const float4* as = (const float4*)a_s;
    const float4* ad = (const float4*)a_d;
    float s = 0.f, d = 0.f;
    #pragma unroll
    for (int c = 0; c < 32; c++) {
        float4 h = row[c];
        float4 sa = as[c], da = ad[c];
        s = fmaf(h.x, sa.x, fmaf(h.y, sa.y, fmaf(h.z, sa.z, fmaf(h.w, sa.w, s))));
        d = fmaf(h.x, da.x, fmaf(h.y, da.y, fmaf(h.z, da.z, fmaf(h.w, da.w, d))));
    }
    g_es2[node] = s;
    g_ed2[node] = d;
}

__device__ __forceinline__ float elu1(float x)  { return x > 0.f ? x : expm1f(x); }
__device__ __forceinline__ float lrelu(float x) { return x > 0.f ? x : NEG_SLOPE * x; }

// ---------------- edge weights (edge-parallel, coalesced) --------------------
// Logits are bounded (|e| < ~10) -> exp() safe without max subtraction.
__global__ void wgt1_kernel() {
    int j = blockIdx.x * blockDim.x + threadIdx.x;
    if (j >= ET) return;
    int src = g_esrc[j], dst = g_edst[j];
    float4 es = *(const float4*)&g_es1[src * 4];
    float4 ed = *(const float4*)&g_ed1[dst * 4];
    float4 w;
    w.x = __expf(lrelu(es.x + ed.x));
    w.y = __expf(lrelu(es.y + ed.y));
    w.z = __expf(lrelu(es.z + ed.z));
    w.w = __expf(lrelu(es.w + ed.w));
    *(float4*)&g_ew1[(size_t)j * 4] = w;
}

__global__ void wgt2_kernel() {
    int j = blockIdx.x * blockDim.x + threadIdx.x;
    if (j >= ET) return;
    int src = g_esrc[j], dst = g_edst[j];
    g_ew2[j] = __expf(lrelu(g_es2[src] + g_ed2[dst]));
}

// ---------------- fused softmax + aggregation (warp per dst) -----------------
__global__ __launch_bounds__(256) void agg1_kernel(const float* __restrict__ b1) {
    int dst  = (blockIdx.x * blockDim.x + threadIdx.x) >> 5;
    int lane = threadIdx.x & 31;
    if (dst >= NN) return;
    int start = g_off[dst], end = g_off[dst + 1];

    // pass A: coalesced sum of precomputed weights
    float s0=0.f,s1=0.f,s2=0.f,s3=0.f;
    for (int j = start + lane; j < end; j += 32) {
        float4 w = *(const float4*)&g_ew1[(size_t)j * 4];
        s0 += w.x; s1 += w.y; s2 += w.z; s3 += w.w;
    }
    #pragma unroll
    for (int off = 16; off; off >>= 1) {
        s0 += __shfl_xor_sync(0xffffffffu, s0, off);
        s1 += __shfl_xor_sync(0xffffffffu, s1, off);
        s2 += __shfl_xor_sync(0xffffffffu, s2, off);
        s3 += __shfl_xor_sync(0xffffffffu, s3, off);
    }
    float i0 = 1.f/s0, i1 = 1.f/s1, i2 = 1.f/s2, i3 = 1.f/s3;

    // pass B: serial edges, contiguous weight loads, half feature gathers
    int hsel = lane >> 4;
    float ia = hsel ? i1 : i0, ib = hsel ? i3 : i2;

    float4 acc0 = make_float4(0.f,0.f,0.f,0.f);
    float4 acc1 = make_float4(0.f,0.f,0.f,0.f);

    #pragma unroll 4
    for (int j = start; j < end; j++) {
        int src = g_esrc[j];
        float4 w4 = *(const float4*)&g_ew1[(size_t)j * 4];
        float wa = (hsel ? w4.y : w4.x) * ia;
        float wb = (hsel ? w4.w : w4.z) * ib;
        const float2* row = (const float2*)(g_h1h + (size_t)src * H1DIM);
        float2 q0 = row[lane];
        float2 q1 = row[lane + 32];
        float2 f0 = __half22float2(*(__half2*)&q0.x);
        float2 f1 = __half22float2(*(__half2*)&q0.y);
        float2 f2 = __half22float2(*(__half2*)&q1.x);
        float2 f3 = __half22float2(*(__half2*)&q1.y);
        acc0.x = fmaf(wa, f0.x, acc0.x); acc0.y = fmaf(wa, f0.y, acc0.y);
        acc0.z = fmaf(wa, f1.x, acc0.z); acc0.w = fmaf(wa, f1.y, acc0.w);
        acc1.x = fmaf(wb, f2.x, acc1.x); acc1.y = fmaf(wb, f2.y, acc1.y);
        acc1.z = fmaf(wb, f3.x, acc1.z); acc1.w = fmaf(wb, f3.y, acc1.w);
    }

    int c0 = lane * 4, c1 = 128 + lane * 4;
    float4 bb0 = *(const float4*)&b1[c0];
    float4 bb1 = *(const float4*)&b1[c1];
    float4 o0 = make_float4(elu1(acc0.x + bb0.x), elu1(acc0.y + bb0.y),
                            elu1(acc0.z + bb0.z), elu1(acc0.w + bb0.w));
    float4 o1 = make_float4(elu1(acc1.x + bb1.x), elu1(acc1.y + bb1.y),
                            elu1(acc1.z + bb1.z), elu1(acc1.w + bb1.w));
    *(float4*)(g_out1 + (size_t)dst * H1DIM + c0) = o0;
    *(float4*)(g_out1 + (size_t)dst * H1DIM + c1) = o1;
}

__global__ __launch_bounds__(256) void agg2_kernel(const float* __restrict__ b2) {
    int dst  = (blockIdx.x * blockDim.x + threadIdx.x) >> 5;
    int lane = threadIdx.x & 31;
    if (dst >= NN) return;
    int start = g_off[dst], end = g_off[dst + 1];

    float s = 0.f;
    for (int j = start + lane; j < end; j += 32)
        s += g_ew2[j];
    #pragma unroll
    for (int off = 16; off; off >>= 1)
        s += __shfl_xor_sync(0xffffffffu, s, off);
    float inv = 1.f / s;

    float4 acc = make_float4(0.f,0.f,0.f,0.f);
    #pragma unroll 4
    for (int j = start; j < end; j++) {
        int src = g_esrc[j];
        float wt = g_ew2[j] * inv;
        const float2* row = (const float2*)(g_h2h + (size_t)src * H2DIM);
        float2 q = row[lane];
        float2 f0 = __half22float2(*(__half2*)&q.x);
        float2 f1 = __half22float2(*(__half2*)&q.y);
        acc.x = fmaf(wt, f0.x, acc.x); acc.y = fmaf(wt, f0.y, acc.y);
        acc.z = fmaf(wt, f1.x, acc.z); acc.w = fmaf(wt, f1.y, acc.w);
    }

    int c0 = lane * 4;
    float4 bb = *(const float4*)&b2[c0];
    float4 o = make_float4(elu1(acc.x + bb.x), elu1(acc.y + bb.y),
                           elu1(acc.z + bb.z), elu1(acc.w + bb.w));
    *(float4*)(g_out2 + (size_t)dst * H2DIM + c0) = o;
}

// ---------------- pooling + FC + log_softmax ---------------------------------
__device__ __forceinline__ int lb_i(const int* a, int n, int v) {
    int lo = 0, hi = n;
    while (lo < hi) { int mid = (lo + hi) >> 1; if (a[mid] < v) lo = mid + 1; else hi = mid; }
    return lo;
}

__global__ void pool_fc_kernel(const int* __restrict__ batch,
                               const float* __restrict__ fc_w,
                               const float* __restrict__ fc_b,
                               float* __restrict__ out)
{
    int g = blockIdx.x;
    int tid = threadIdx.x;
    __shared__ float sp[128];
    __shared__ float slog[10];
    int lo = lb_i(batch, NN, g);
    int hi = lb_i(batch, NN, g + 1);
    float s = 0.f;
    for (int i = lo; i < hi; i++) s += g_out2[(size_t)i * H2DIM + tid];
    float cnt = (float)(hi - lo);
    sp[tid] = s / fmaxf(cnt, 1.f);
    __syncthreads();
    if (tid < 10) {
        float l = fc_b[tid];
        #pragma unroll 16
        for (int c = 0; c < 128; c++) l = fmaf(sp[c], fc_w[c * 10 + tid], l);
        slog[tid] = l;
    }
    __syncthreads();
    if (tid == 0) {
        float mx = -1e30f;
        #pragma unroll
        for (int k = 0; k < 10; k++) mx = fmaxf(mx, slog[k]);
        float sum = 0.f;
        #pragma unroll
        for (int k = 0; k < 10; k++) sum += expf(slog[k] - mx);
        float lse = mx + logf(sum);
        #pragma unroll
        for (int k = 0; k < 10; k++) out[g * 10 + k] = slog[k] - lse;
    }
}

// ---------------- launch -----------------------------------------------------
extern "C" void kernel_launch(void* const* d_in, const int* in_sizes, int n_in,
                              void* d_out, int out_size)
{
    const float* x     = (const float*)d_in[0];
    const int*   ei    = (const int*)d_in[1];
    const int*   batch = (const int*)d_in[2];
    const float* W1    = (const float*)d_in[3];
    const float* a_s1  = (const float*)d_in[4];
    const float* a_d1  = (const float*)d_in[5];
    const float* b1    = (const float*)d_in[6];
    const float* W2    = (const float*)d_in[7];
    const float* a_s2  = (const float*)d_in[8];
    const float* a_d2  = (const float*)d_in[9];
    const float* b2    = (const float*)d_in[10];
    const float* fc_w  = (const float*)d_in[11];
    const float* fc_b  = (const float*)d_in[12];
    float* out = (float*)d_out;

    zero_counts_kernel<<<(NN + 255) / 256, 256>>>();
    count_kernel<<<(ET + 255) / 256, 256>>>(ei);
    scan1_kernel<<<NBLK, 1024>>>();
    scan2_kernel<<<1, 64>>>();
    scan3_kernel<<<(NN + 255) / 256, 256>>>();
    fill_kernel<<<(ET + 255) / 256, 256>>>(ei);

    {
        dim3 grid(H1DIM / BN, (NN + BM - 1) / BM);
        gemm1_kernel<<<grid, 256>>>(x, W1);
    }
    coef1_kernel<<<(NN * 4 + 255) / 256, 256>>>(a_s1, a_d1);
    wgt1_kernel<<<(ET + 255) / 256, 256>>>();
    agg1_kernel<<<(NN * 32 + 255) / 256, 256>>>(b1);

    {
        dim3 grid(H2DIM / BN, (NN + BM - 1) / BM);
        gemm2_kernel<<<grid, 256>>>(W2);
    }
    coef2_kernel<<<(NN + 255) / 256, 256>>>(a_s2, a_d2);
    wgt2_kernel<<<(ET + 255) / 256, 256>>>();
    agg2_kernel<<<(NN * 32 + 255) / 256, 256>>>(b2);

    pool_fc_kernel<<<NGRAPH, 128>>>(batch, fc_w, fc_b, out);
}

// round 14
// speedup vs baseline: 1.5798x; 1.0608x over previous
#include <cuda_runtime.h>
#include <cuda_fp16.h>
#include <math.h>
#include <stdint.h>

#define NN 50000
#define EE 800000
#define ET (EE + NN)
#define FIN 128
#define H1DIM 256
#define H2DIM 128
#define NGRAPH 64
#define NEG_SLOPE 0.2f
#define NBLK 49   // ceil(NN/1024)

// ---------------- scratch ----------------------------------------------------
__device__ __align__(16) float  g_h1[(size_t)NN * H1DIM];
__device__ __align__(16) __half g_h1h[(size_t)NN * H1DIM];
__device__ __align__(16) float  g_out1[(size_t)NN * H1DIM];
__device__ __align__(16) float  g_h2[(size_t)NN * H2DIM];
__device__ __align__(16) __half g_h2h[(size_t)NN * H2DIM];
__device__ __align__(16) float  g_out2[(size_t)NN * H2DIM];
__device__ __align__(16) float  g_es1[NN * 4];
__device__ __align__(16) float  g_ed1[NN * 4];
__device__ float g_es2[NN];
__device__ float g_ed2[NN];
__device__ int   g_cnt[NN];
__device__ int   g_off[NN + 1];
__device__ int   g_rank[ET];
__device__ int   g_esrc[ET];
__device__ int   g_bsum[NBLK];
__device__ int   g_boff[NBLK];

// ---------------- CSR build --------------------------------------------------
__global__ void zero_counts_kernel() {
    int i = blockIdx.x * blockDim.x + threadIdx.x;
    if (i < NN) g_cnt[i] = 0;
}

__global__ void count_kernel(const int* __restrict__ ei) {
    int e = blockIdx.x * blockDim.x + threadIdx.x;
    if (e >= ET) return;
    int dst = (e < EE) ? ei[EE + e] : (e - EE);
    g_rank[e] = atomicAdd(&g_cnt[dst], 1);
}

__global__ void scan1_kernel() {
    __shared__ int sdata[1024];
    int b = blockIdx.x, tid = threadIdx.x;
    int i = b * 1024 + tid;
    int v = (i < NN) ? g_cnt[i] : 0;
    sdata[tid] = v;
    __syncthreads();
    #pragma unroll
    for (int d = 1; d < 1024; d <<= 1) {
        int t = (tid >= d) ? sdata[tid - d] : 0;
        __syncthreads();
        sdata[tid] += t;
        __syncthreads();
    }
    if (i < NN) g_off[i] = sdata[tid] - v;
    if (tid == 1023) g_bsum[b] = sdata[1023];
}

__global__ void scan2_kernel() {
    int t = threadIdx.x;            // 64 threads
    int lane = t & 31, w = t >> 5;
    int v = (t < NBLK) ? g_bsum[t] : 0;
    int x = v;
    #pragma unroll
    for (int d = 1; d < 32; d <<= 1) {
        int y = __shfl_up_sync(0xffffffffu, x, d);
        if (lane >= d) x += y;
    }
    __shared__ int wt[2];
    if (lane == 31) wt[w] = x;
    __syncthreads();
    if (w == 1) x += wt[0];
    if (t < NBLK) g_boff[t] = x - v;
}

__global__ void scan3_kernel() {
    int i = blockIdx.x * blockDim.x + threadIdx.x;
    if (i >= NN) return;
    g_off[i] = g_off[i] + g_boff[i >> 10];
    if (i == 0) g_off[NN] = ET;
}

__global__ void fill_kernel(const int* __restrict__ ei) {
    int e = blockIdx.x * blockDim.x + threadIdx.x;
    if (e >= ET) return;
    int src, dst;
    if (e < EE) { src = ei[e]; dst = ei[EE + e]; }
    else        { src = e - EE; dst = e - EE; }
    g_esrc[g_off[dst] + g_rank[e]] = src;
}

// ---------------- single-pass TF32 tensor-core GEMM --------------------------
#define BM 128
#define BN 128
#define BK 16
#define PADK 8

__device__ __forceinline__ float4 ldg4(const float* p) { return *(const float4*)p; }

__device__ __forceinline__ uint32_t f2tf(float x) {
    uint32_t u;
    asm("cvt.rna.tf32.f32 %0, %1;" : "=r"(u) : "f"(x));
    return u;
}

__device__ __forceinline__ void mma8(float* c, const uint32_t* a, const uint32_t* b) {
    asm volatile(
        "mma.sync.aligned.m16n8k8.row.col.f32.tf32.tf32.f32 "
        "{%0,%1,%2,%3},{%4,%5,%6,%7},{%8,%9},{%0,%1,%2,%3};"
        : "+f"(c[0]), "+f"(c[1]), "+f"(c[2]), "+f"(c[3])
        : "r"(a[0]), "r"(a[1]), "r"(a[2]), "r"(a[3]), "r"(b[0]), "r"(b[1]));
}

__device__ __forceinline__ void gemm_body(
    const float* __restrict__ A, const float* __restrict__ B,
    float* __restrict__ C, __half* __restrict__ Ch, int M, int N, int K)
{
    __shared__ uint32_t Ahi[2][BK][BM + PADK];
    __shared__ uint32_t Bhi[2][BK][BN + PADK];

    const int tid  = threadIdx.x;
    const int lane = tid & 31;
    const int wid  = tid >> 5;
    const int warp_m = wid >> 2;
    const int warp_n = wid & 3;
    const int bm = blockIdx.y * BM, bn = blockIdx.x * BN;
    const int tg = lane & 3;
    const int tr = lane >> 2;

    const int ar = tid & 127, ac = (tid >> 7) * 8;
    const int br = tid >> 4, bc = (tid & 15) * 8;

    float c[4][4][4];
    #pragma unroll
    for (int mt = 0; mt < 4; mt++)
        #pragma unroll
        for (int nt = 0; nt < 4; nt++)
            #pragma unroll
            for (int r = 0; r < 4; r++) c[mt][nt][r] = 0.f;

    float4 pa0, pa1, pb0, pb1;
    auto LDG = [&](int k0) {
        if (bm + ar < M) {
            pa0 = ldg4(A + (size_t)(bm + ar) * K + k0 + ac);
            pa1 = ldg4(A + (size_t)(bm + ar) * K + k0 + ac + 4);
        } else {
            pa0 = make_float4(0.f,0.f,0.f,0.f);
            pa1 = pa0;
        }
        pb0 = ldg4(B + (size_t)(k0 + br) * N + bn + bc);
        pb1 = ldg4(B + (size_t)(k0 + br) * N + bn + bc + 4);
    };
    auto STS = [&](int buf) {
        float av[8] = {pa0.x, pa0.y, pa0.z, pa0.w, pa1.x, pa1.y, pa1.z, pa1.w};
        #pragma unroll
        for (int i = 0; i < 8; i++)
            Ahi[buf][ac + i][ar] = f2tf(av[i]);
        *(uint4*)&Bhi[buf][br][bc] =
            make_uint4(f2tf(pb0.x), f2tf(pb0.y), f2tf(pb0.z), f2tf(pb0.w));
        *(uint4*)&Bhi[buf][br][bc + 4] =
            make_uint4(f2tf(pb1.x), f2tf(pb1.y), f2tf(pb1.z), f2tf(pb1.w));
    };

    LDG(0);
    STS(0);
    __syncthreads();

    const int T = K / BK;
    for (int t = 0; t < T; t++) {
        int cur = t & 1;
        if (t + 1 < T) LDG((t + 1) * BK);

        #pragma unroll
        for (int ks = 0; ks < 2; ks++) {
            const int kk = ks * 8;
            uint32_t a[4][4], b[4][2];
            #pragma unroll
            for (int mt = 0; mt < 4; mt++) {
                int mb = warp_m * 64 + mt * 16;
                a[mt][0] = Ahi[cur][kk + tg    ][mb + tr];
                a[mt][1] = Ahi[cur][kk + tg    ][mb + tr + 8];
                a[mt][2] = Ahi[cur][kk + tg + 4][mb + tr];
                a[mt][3] = Ahi[cur][kk + tg + 4][mb + tr + 8];
            }
            #pragma unroll
            for (int nt = 0; nt < 4; nt++) {
                int nb = warp_n * 32 + nt * 8;
                b[nt][0] = Bhi[cur][kk + tg    ][nb + tr];
                b[nt][1] = Bhi[cur][kk + tg + 4][nb + tr];
            }
            #pragma unroll
            for (int mt = 0; mt < 4; mt++)
                #pragma unroll
                for (int nt = 0; nt < 4; nt++)
                    mma8(c[mt][nt], a[mt], b[nt]);
        }

        if (t + 1 < T) { STS(cur ^ 1); __syncthreads(); }
    }

    #pragma unroll
    for (int mt = 0; mt < 4; mt++) {
        int row0 = bm + warp_m * 64 + mt * 16 + tr;
        int row1 = row0 + 8;
        #pragma unroll
        for (int nt = 0; nt < 4; nt++) {
            int col = bn + warp_n * 32 + nt * 8 + tg * 2;
            if (row0 < M) {
                *(float2*)(C + (size_t)row0 * N + col) = make_float2(c[mt][nt][0], c[mt][nt][1]);
                *(__half2*)(Ch + (size_t)row0 * N + col) =
                    __float22half2_rn(make_float2(c[mt][nt][0], c[mt][nt][1]));
            }
            if (row1 < M) {
                *(float2*)(C + (size_t)row1 * N + col) = make_float2(c[mt][nt][2], c[mt][nt][3]);
                *(__half2*)(Ch + (size_t)row1 * N + col) =
                    __float22half2_rn(make_float2(c[mt][nt][2], c[mt][nt][3]));
            }
        }
    }
}

__global__ __launch_bounds__(256) void gemm1_kernel(
    const float* __restrict__ x, const float* __restrict__ W1)
{
    gemm_body(x, W1, g_h1, g_h1h, NN, H1DIM, FIN);
}

__global__ __launch_bounds__(256) void gemm2_kernel(
    const float* __restrict__ W2)
{
    gemm_body(g_out1, W2, g_h2, g_h2h, NN, H2DIM, H1DIM);
}

// ---------------- attention coefficients ------------------------------------
__global__ void coef1_kernel(const float* __restrict__ a_s, const float* __restrict__ a_d) {
    int idx = blockIdx.x * blockDim.x + threadIdx.x;
    if (idx >= NN * 4) return;
    int node = idx >> 2, head = idx & 3;
    const float4* row = (const float4*)(g_h1 + (size_t)node * H1DIM + head * 64);
    const float4* as = (const float4*)(a_s + head * 64);
    const float4* ad = (const float4*)(a_d + head * 64);
    float s = 0.f, d = 0.f;
    #pragma unroll
    for (int c = 0; c < 16; c++) {
        float4 h = row[c];
        float4 sa = as[c], da = ad[c];
        s = fmaf(h.x, sa.x, fmaf(h.y, sa.y, fmaf(h.z, sa.z, fmaf(h.w, sa.w, s))));
        d = fmaf(h.x, da.x, fmaf(h.y, da.y, fmaf(h.z, da.z, fmaf(h.w, da.w, d))));
    }
    g_es1[idx] = s;
    g_ed1[idx] = d;
}

__global__ void coef2_kernel(const float* __restrict__ a_s, const float* __restrict__ a_d) {
    int node = blockIdx.x * blockDim.x + threadIdx.x;
    if (node >= NN) return;
    const float4* row = (const float4*)(g_h2 + (size_t)node * H2DIM);
    const float4* as = (const float4*)a_s;
    const float4* ad = (const float4*)a_d;
    float s = 0.f, d = 0.f;
    #pragma unroll
    for (int c = 0; c < 32; c++) {
        float4 h = row[c];
        float4 sa = as[c], da = ad[c];
        s = fmaf(h.x, sa.x, fmaf(h.y, sa.y, fmaf(h.z, sa.z, fmaf(h.w, sa.w, s))));
        d = fmaf(h.x, da.x, fmaf(h.y, da.y, fmaf(h.z, da.z, fmaf(h.w, da.w, d))));
    }
    g_es2[node] = s;
    g_ed2[node] = d;
}

__device__ __forceinline__ float elu1(float x)  { return x > 0.f ? x : expm1f(x); }
__device__ __forceinline__ float lrelu(float x) { return x > 0.f ? x : NEG_SLOPE * x; }

// ---------------- fused softmax + aggregation (warp per dst) -----------------
// Logits are bounded (|e| < ~10) -> exp() is safe without max subtraction.
__global__ __launch_bounds__(256) void agg1_kernel(const float* __restrict__ b1) {
    int dst  = (blockIdx.x * blockDim.x + threadIdx.x) >> 5;
    int lane = threadIdx.x & 31;
    if (dst >= NN) return;
    int start = g_off[dst], end = g_off[dst + 1];
    float4 ed = *(const float4*)&g_ed1[dst * 4];

    // pass A: lane-parallel exp sums
    float s0=0.f,s1=0.f,s2=0.f,s3=0.f;
    for (int j = start + lane; j < end; j += 32) {
        int src = g_esrc[j];
        float4 es = *(const float4*)&g_es1[src * 4];
        s0 += __expf(lrelu(es.x + ed.x));
        s1 += __expf(lrelu(es.y + ed.y));
        s2 += __expf(lrelu(es.z + ed.z));
        s3 += __expf(lrelu(es.w + ed.w));
    }
    #pragma unroll
    for (int off = 16; off; off >>= 1) {
        s0 += __shfl_xor_sync(0xffffffffu, s0, off);
        s1 += __shfl_xor_sync(0xffffffffu, s1, off);
        s2 += __shfl_xor_sync(0xffffffffu, s2, off);
        s3 += __shfl_xor_sync(0xffffffffu, s3, off);
    }
    float i0 = 1.f/s0, i1 = 1.f/s1, i2 = 1.f/s2, i3 = 1.f/s3;

    // pass B: serial edges, feature-parallel half gathers
    int hsel = lane >> 4;
    float ia = hsel ? i1 : i0, ib = hsel ? i3 : i2;
    float eda = hsel ? ed.y : ed.x, edb = hsel ? ed.w : ed.z;

    float4 acc0 = make_float4(0.f,0.f,0.f,0.f);
    float4 acc1 = make_float4(0.f,0.f,0.f,0.f);

    #pragma unroll 4
    for (int j = start; j < end; j++) {
        int src = g_esrc[j];
        float4 es = *(const float4*)&g_es1[src * 4];
        float es_a = hsel ? es.y : es.x;
        float es_b = hsel ? es.w : es.z;
        float wa = __expf(lrelu(es_a + eda)) * ia;
        float wb = __expf(lrelu(es_b + edb)) * ib;
        const float2* row = (const float2*)(g_h1h + (size_t)src * H1DIM);
        float2 q0 = row[lane];
        float2 q1 = row[lane + 32];
        float2 f0 = __half22float2(*(__half2*)&q0.x);
        float2 f1 = __half22float2(*(__half2*)&q0.y);
        float2 f2 = __half22float2(*(__half2*)&q1.x);
        float2 f3 = __half22float2(*(__half2*)&q1.y);
        acc0.x = fmaf(wa, f0.x, acc0.x); acc0.y = fmaf(wa, f0.y, acc0.y);
        acc0.z = fmaf(wa, f1.x, acc0.z); acc0.w = fmaf(wa, f1.y, acc0.w);
        acc1.x = fmaf(wb, f2.x, acc1.x); acc1.y = fmaf(wb, f2.y, acc1.y);
        acc1.z = fmaf(wb, f3.x, acc1.z); acc1.w = fmaf(wb, f3.y, acc1.w);
    }

    int c0 = lane * 4, c1 = 128 + lane * 4;
    float4 bb0 = *(const float4*)&b1[c0];
    float4 bb1 = *(const float4*)&b1[c1];
    float4 o0 = make_float4(elu1(acc0.x + bb0.x), elu1(acc0.y + bb0.y),
                            elu1(acc0.z + bb0.z), elu1(acc0.w + bb0.w));
    float4 o1 = make_float4(elu1(acc1.x + bb1.x), elu1(acc1.y + bb1.y),
                            elu1(acc1.z + bb1.z), elu1(acc1.w + bb1.w));
    *(float4*)(g_out1 + (size_t)dst * H1DIM + c0) = o0;
    *(float4*)(g_out1 + (size_t)dst * H1DIM + c1) = o1;
}

__global__ __launch_bounds__(256) void agg2_kernel(const float* __restrict__ b2) {
    int dst  = (blockIdx.x * blockDim.x + threadIdx.x) >> 5;
    int lane = threadIdx.x & 31;
    if (dst >= NN) return;
    int start = g_off[dst], end = g_off[dst + 1];
    float edv = g_ed2[dst];

    float s = 0.f;
    for (int j = start + lane; j < end; j += 32) {
        int src = g_esrc[j];
        s += __expf(lrelu(g_es2[src] + edv));
    }
    #pragma unroll
    for (int off = 16; off; off >>= 1)
        s += __shfl_xor_sync(0xffffffffu, s, off);
    float inv = 1.f / s;

    float4 acc = make_float4(0.f,0.f,0.f,0.f);
    #pragma unroll 4
    for (int j = start; j < end; j++) {
        int src = g_esrc[j];
        float wt = __expf(lrelu(g_es2[src] + edv)) * inv;
        const float2* row = (const float2*)(g_h2h + (size_t)src * H2DIM);
        float2 q = row[lane];
        float2 f0 = __half22float2(*(__half2*)&q.x);
        float2 f1 = __half22float2(*(__half2*)&q.y);
        acc.x = fmaf(wt, f0.x, acc.x); acc.y = fmaf(wt, f0.y, acc.y);
        acc.z = fmaf(wt, f1.x, acc.z); acc.w = fmaf(wt, f1.y, acc.w);
    }

    int c0 = lane * 4;
    float4 bb = *(const float4*)&b2[c0];
    float4 o = make_float4(elu1(acc.x + bb.x), elu1(acc.y + bb.y),
                           elu1(acc.z + bb.z), elu1(acc.w + bb.w));
    *(float4*)(g_out2 + (size_t)dst * H2DIM + c0) = o;
}

// ---------------- pooling + FC + log_softmax ---------------------------------
__device__ __forceinline__ int lb_i(const int* a, int n, int v) {
    int lo = 0, hi = n;
    while (lo < hi) { int mid = (lo + hi) >> 1; if (a[mid] < v) lo = mid + 1; else hi = mid; }
    return lo;
}

__global__ void pool_fc_kernel(const int* __restrict__ batch,
                               const float* __restrict__ fc_w,
                               const float* __restrict__ fc_b,
                               float* __restrict__ out)
{
    int g = blockIdx.x;
    int tid = threadIdx.x;
    __shared__ float sp[128];
    __shared__ float slog[10];
    int lo = lb_i(batch, NN, g);
    int hi = lb_i(batch, NN, g + 1);
    float s = 0.f;
    for (int i = lo; i < hi; i++) s += g_out2[(size_t)i * H2DIM + tid];
    float cnt = (float)(hi - lo);
    sp[tid] = s / fmaxf(cnt, 1.f);
    __syncthreads();
    if (tid < 10) {
        float l = fc_b[tid];
        #pragma unroll 16
        for (int c = 0; c < 128; c++) l = fmaf(sp[c], fc_w[c * 10 + tid], l);
        slog[tid] = l;
    }
    __syncthreads();
    if (tid == 0) {
        float mx = -1e30f;
        #pragma unroll
        for (int k = 0; k < 10; k++) mx = fmaxf(mx, slog[k]);
        float sum = 0.f;
        #pragma unroll
        for (int k = 0; k < 10; k++) sum += expf(slog[k] - mx);
        float lse = mx + logf(sum);
        #pragma unroll
        for (int k = 0; k < 10; k++) out[g * 10 + k] = slog[k] - lse;
    }
}

// ---------------- launch (two-stream fork/join for CSR || GEMM1) -------------
extern "C" void kernel_launch(void* const* d_in, const int* in_sizes, int n_in,
                              void* d_out, int out_size)
{
    const float* x     = (const float*)d_in[0];
    const int*   ei    = (const int*)d_in[1];
    const int*   batch = (const int*)d_in[2];
    const float* W1    = (const float*)d_in[3];
    const float* a_s1  = (const float*)d_in[4];
    const float* a_d1  = (const float*)d_in[5];
    const float* b1    = (const float*)d_in[6];
    const float* W2    = (const float*)d_in[7];
    const float* a_s2  = (const float*)d_in[8];
    const float* a_d2  = (const float*)d_in[9];
    const float* b2    = (const float*)d_in[10];
    const float* fc_w  = (const float*)d_in[11];
    const float* fc_b  = (const float*)d_in[12];
    float* out = (float*)d_out;

    // Side stream + events created per call (host objects only; kernel_launch
    // is invoked a bounded number of times, so not freeing them is safe and
    // avoids destroying capture-participating objects mid-capture).
    cudaStream_t s2;
    cudaStreamCreateWithFlags(&s2, cudaStreamNonBlocking);
    cudaEvent_t evFork, evJoin;
    cudaEventCreateWithFlags(&evFork, cudaEventDisableTiming);
    cudaEventCreateWithFlags(&evJoin, cudaEventDisableTiming);

    // fork: CSR chain on s2, GEMM1+coef1 on the origin stream
    cudaEventRecord(evFork, 0);
    cudaStreamWaitEvent(s2, evFork, 0);

    zero_counts_kernel<<<(NN + 255) / 256, 256, 0, s2>>>();
    count_kernel<<<(ET + 255) / 256, 256, 0, s2>>>(ei);
    scan1_kernel<<<NBLK, 1024, 0, s2>>>();
    scan2_kernel<<<1, 64, 0, s2>>>();
    scan3_kernel<<<(NN + 255) / 256, 256, 0, s2>>>();
    fill_kernel<<<(ET + 255) / 256, 256, 0, s2>>>(ei);

    {
        dim3 grid(H1DIM / BN, (NN + BM - 1) / BM);
        gemm1_kernel<<<grid, 256>>>(x, W1);
    }
    coef1_kernel<<<(NN * 4 + 255) / 256, 256>>>(a_s1, a_d1);

    // join: agg1 needs g_off/g_esrc (s2) and es1/ed1 (origin)
    cudaEventRecord(evJoin, s2);
    cudaStreamWaitEvent(0, evJoin, 0);

    agg1_kernel<<<(NN * 32 + 255) / 256, 256>>>(b1);

    {
        dim3 grid(H2DIM / BN, (NN + BM - 1) / BM);
        gemm2_kernel<<<grid, 256>>>(W2);
    }
    coef2_kernel<<<(NN + 255) / 256, 256>>>(a_s2, a_d2);
    agg2_kernel<<<(NN * 32 + 255) / 256, 256>>>(b2);

    pool_fc_kernel<<<NGRAPH, 128>>>(batch, fc_w, fc_b, out);
}